// round 12
// baseline (speedup 1.0000x reference)
#include <cuda_runtime.h>
#include <cuda_bf16.h>
#include <mma.h>
#include <math.h>
#include <cstdint>

using namespace nvcuda;

#define S_LEN 2048
#define D_DIM 1024
#define NHEAD 16
#define HD 64
#define MROWS 4096
// 0.125 (1/sqrt(64)) * log2(e), folded into the Q projection epilogue
#define QSCALE 0.1803368801111244f

// Scratch (device globals: no allocations allowed)
__device__ __nv_bfloat16 g_q[MROWS * D_DIM];    // [b,h,s,d] bf16, pre-scaled
__device__ __nv_bfloat16 g_k[MROWS * D_DIM];    // [b,h,s,d] bf16
__device__ __nv_bfloat16 g_v[MROWS * D_DIM];    // [b,h,s,d] bf16
__device__ __nv_bfloat16 g_ctx[MROWS * D_DIM];  // [b,s,h*64+d] bf16
__device__ float g_x[MROWS * D_DIM];            // pre-LN fp32
__device__ uint32_t g_mbits[2 * S_LEN * (S_LEN / 32)];  // packed mask bits
// bf16 copies of inputs & weights (cvt once, consumed by cp.async GEMMs)
__device__ __nv_bfloat16 g_qin[MROWS * D_DIM];
__device__ __nv_bfloat16 g_kin[MROWS * D_DIM];
__device__ __nv_bfloat16 g_vin[MROWS * D_DIM];
__device__ __nv_bfloat16 g_wbf[4 * D_DIM * D_DIM];

// ---------------------------------------------------------------------------
// helpers
// ---------------------------------------------------------------------------
__device__ __forceinline__ uint32_t smem_u32(const void* p) {
    return (uint32_t)__cvta_generic_to_shared(p);
}
__device__ __forceinline__ void cp16(uint32_t dst, const void* src) {
    asm volatile("cp.async.cg.shared.global [%0], [%1], 16;"
                 :: "r"(dst), "l"(src) : "memory");
}
#define CP_COMMIT() asm volatile("cp.async.commit_group;" ::: "memory")
#define CP_WAIT0()  asm volatile("cp.async.wait_group 0;" ::: "memory")
#define CP_WAIT1()  asm volatile("cp.async.wait_group 1;" ::: "memory")

__device__ __forceinline__ void ldsm4(uint32_t& r0, uint32_t& r1,
                                      uint32_t& r2, uint32_t& r3, uint32_t a) {
    asm volatile("ldmatrix.sync.aligned.m8n8.x4.shared.b16 {%0,%1,%2,%3}, [%4];"
                 : "=r"(r0), "=r"(r1), "=r"(r2), "=r"(r3) : "r"(a));
}
__device__ __forceinline__ void ldsm4t(uint32_t& r0, uint32_t& r1,
                                       uint32_t& r2, uint32_t& r3, uint32_t a) {
    asm volatile("ldmatrix.sync.aligned.m8n8.x4.trans.shared.b16 {%0,%1,%2,%3}, [%4];"
                 : "=r"(r0), "=r"(r1), "=r"(r2), "=r"(r3) : "r"(a));
}
// D(16x8,f32) += A(16x16,bf16) * B(16x8,bf16)
__device__ __forceinline__ void mma16(float* d, uint32_t a0, uint32_t a1,
                                      uint32_t a2, uint32_t a3,
                                      uint32_t b0, uint32_t b1) {
    asm volatile(
        "mma.sync.aligned.m16n8k16.row.col.f32.bf16.bf16.f32 "
        "{%0,%1,%2,%3}, {%4,%5,%6,%7}, {%8,%9}, {%0,%1,%2,%3};"
        : "+f"(d[0]), "+f"(d[1]), "+f"(d[2]), "+f"(d[3])
        : "r"(a0), "r"(a1), "r"(a2), "r"(a3), "r"(b0), "r"(b1));
}
// pack two floats -> bf16x2 (lo in low 16 bits)
__device__ __forceinline__ uint32_t packbf(float lo, float hi) {
    uint32_t r;
    asm("cvt.rn.bf16x2.f32 %0, %1, %2;" : "=r"(r) : "f"(hi), "f"(lo));
    return r;
}
// packed 2^x on bf16x2 (subnormal results flushed to 0)
__device__ __forceinline__ uint32_t ex2bf2(uint32_t x) {
    uint32_t r;
    asm("ex2.approx.ftz.bf16x2 %0, %1;" : "=r"(r) : "r"(x));
    return r;
}

// ===========================================================================
// cvt: fp32 -> bf16 copies. z 0..2: Q/K/V inputs (4M elems); 3..6: weights (1M)
// ===========================================================================
__global__ __launch_bounds__(256) void cvt_k(
    const float* __restrict__ Q, const float* __restrict__ K,
    const float* __restrict__ V,
    const float* __restrict__ Wq, const float* __restrict__ Wk,
    const float* __restrict__ Wv, const float* __restrict__ Wo)
{
    const int z = blockIdx.y;
    const float* src;
    __nv_bfloat16* dst;
    int n4;
    if (z < 3) {
        src = (z == 0) ? Q : (z == 1) ? K : V;
        dst = (z == 0) ? g_qin : (z == 1) ? g_kin : g_vin;
        n4 = (MROWS * D_DIM) / 4;
    } else {
        src = (z == 3) ? Wq : (z == 4) ? Wk : (z == 5) ? Wv : Wo;
        dst = g_wbf + (size_t)(z - 3) * (D_DIM * D_DIM);
        n4 = (D_DIM * D_DIM) / 4;
    }
    const int idx = blockIdx.x * 256 + threadIdx.x;
    if (idx >= n4) return;
    const float4 v = ((const float4*)src)[idx];
    uint2 p;
    p.x = packbf(v.x, v.y);
    p.y = packbf(v.z, v.w);
    ((uint2*)dst)[idx] = p;
}

// ===========================================================================
// Mask bit-pack: g_mbits[b*2048+row][word] = ballot of mask[row][word*32+lane]
// ===========================================================================
__global__ __launch_bounds__(256) void mb_k(const int* __restrict__ mask)
{
    const int rr = blockIdx.x;
    const int w = threadIdx.x >> 5;
    const int lane = threadIdx.x & 31;
    const int* mrow = mask + (size_t)rr * S_LEN;
    uint32_t* obase = g_mbits + (size_t)rr * (S_LEN / 32);
#pragma unroll
    for (int i = 0; i < 8; i++) {
        const int word = w + i * 8;
        const uint32_t bal =
            __ballot_sync(0xffffffffu, mrow[word * 32 + lane] != 0);
        if (lane == 0) obase[word] = bal;
    }
}

// ===========================================================================
// bf16 GEMM, 3-stage cp.async pipeline, ONE syncthreads per K-chunk.
// CTA 128x128, K-chunk 64, 8 warps of 32x64 (WMMA m16n16k16).
// A stage = 128x72 bf16 = 18432 B; B stage = 64x136 bf16 = 17408 B.
// smem bytes: A @ {0, 18432, 36864}; B @ {55296, 72704, 90112}; total 107520.
// Cs alias (128x136 fp32 = 69632 B) fits.
// ===========================================================================
#define MM_SMEM_BYTES 107520

template <int IS_O>
__global__ __launch_bounds__(256, 2) void mm2_k(
    const float* __restrict__ b0p, const float* __restrict__ b1p,
    const float* __restrict__ b2p, const float* __restrict__ resid)
{
    extern __shared__ __nv_bfloat16 smh[];
    const uint32_t sb = smem_u32(smh);
    const uint32_t as_b[3] = {sb, sb + 18432, sb + 36864};
    const uint32_t bs_b[3] = {sb + 55296, sb + 72704, sb + 90112};
    float* Cs = (float*)smh;

    const int tid = threadIdx.x;
    const int wid = tid >> 5;
    const int wm0 = (wid & 3) * 32;
    const int wn0 = (wid >> 2) * 64;
    const int brow = blockIdx.y * 128;
    const int bcol = blockIdx.x * 128;
    const int z = IS_O ? 3 : blockIdx.z;

    const __nv_bfloat16* A =
        IS_O ? g_ctx : (z == 0) ? g_qin : (z == 1) ? g_kin : g_vin;
    const __nv_bfloat16* W = g_wbf + (size_t)z * (D_DIM * D_DIM);
    const float* bias = IS_O ? b0p : (z == 0) ? b0p : (z == 1) ? b1p : b2p;

    const int ar = tid >> 1;
    const int ac = (tid & 1) * 4;
    const int br_ = tid >> 2;
    const int bc_ = (tid & 3) * 4;

    auto issueA = [&](int buf, int kc) {
        const __nv_bfloat16* srcr = A + (size_t)(brow + ar) * D_DIM + kc * 64;
        const uint32_t dstr = as_b[buf] + ar * 144;
#pragma unroll
        for (int c = 0; c < 4; c++)
            cp16(dstr + (ac + c) * 16, srcr + (ac + c) * 8);
    };
    auto issueB = [&](int buf, int kc) {
        const __nv_bfloat16* srcr = W + (size_t)(kc * 64 + br_) * D_DIM + bcol;
        const uint32_t dstr = bs_b[buf] + br_ * 272;
#pragma unroll
        for (int c = 0; c < 4; c++)
            cp16(dstr + (bc_ + c) * 16, srcr + (bc_ + c) * 8);
    };

    wmma::fragment<wmma::accumulator, 16, 16, 16, float> acc[2][4];
#pragma unroll
    for (int mi = 0; mi < 2; mi++)
#pragma unroll
        for (int ni = 0; ni < 4; ni++)
            wmma::fill_fragment(acc[mi][ni], 0.0f);

    issueA(0, 0);
    issueB(0, 0);
    CP_COMMIT();
    issueA(1, 1);
    issueB(1, 1);
    CP_COMMIT();

    int cur = 0;
    for (int kc = 0; kc < 16; kc++) {
        if (kc < 15) CP_WAIT1(); else CP_WAIT0();
        __syncthreads();
        if (kc + 2 < 16) {
            int tgt = cur + 2;
            if (tgt >= 3) tgt -= 3;
            issueA(tgt, kc + 2);
            issueB(tgt, kc + 2);
            CP_COMMIT();
        }

        // element-domain pointers: A stage = 9216 elems; B stages start at
        // elem 27648, stage = 8704 elems
        const __nv_bfloat16* As = smh + cur * 9216;
        const __nv_bfloat16* Bs = smh + 27648 + cur * 8704;
#pragma unroll
        for (int k0 = 0; k0 < 64; k0 += 16) {
            wmma::fragment<wmma::matrix_a, 16, 16, 16, __nv_bfloat16,
                           wmma::row_major> af[2];
            wmma::fragment<wmma::matrix_b, 16, 16, 16, __nv_bfloat16,
                           wmma::row_major> bf[4];
#pragma unroll
            for (int mi = 0; mi < 2; mi++)
                wmma::load_matrix_sync(af[mi], &As[(wm0 + mi * 16) * 72 + k0], 72);
#pragma unroll
            for (int ni = 0; ni < 4; ni++)
                wmma::load_matrix_sync(bf[ni], &Bs[k0 * 136 + wn0 + ni * 16], 136);
#pragma unroll
            for (int mi = 0; mi < 2; mi++)
#pragma unroll
                for (int ni = 0; ni < 4; ni++)
                    wmma::mma_sync(acc[mi][ni], af[mi], bf[ni], acc[mi][ni]);
        }
        cur = (cur == 2) ? 0 : cur + 1;
    }
    __syncthreads();   // all reads done before Cs alias is written

#pragma unroll
    for (int mi = 0; mi < 2; mi++)
#pragma unroll
        for (int ni = 0; ni < 4; ni++)
            wmma::store_matrix_sync(&Cs[(wm0 + mi * 16) * 136 + wn0 + ni * 16],
                                    acc[mi][ni], 136, wmma::mem_row_major);
    __syncthreads();

    const float oscale = (!IS_O && z == 0) ? QSCALE : 1.0f;
#pragma unroll
    for (int j = 0; j < 16; j++) {
        const int lin = tid + j * 256;
        const int r = lin >> 5;
        const int c4 = (lin & 31) << 2;
        const int row = brow + r;
        const int col = bcol + c4;
        float4 cv = *(float4*)&Cs[r * 136 + c4];
        const float4 bi = *(const float4*)(bias + col);
        cv.x = (cv.x + bi.x) * oscale;
        cv.y = (cv.y + bi.y) * oscale;
        cv.z = (cv.z + bi.z) * oscale;
        cv.w = (cv.w + bi.w) * oscale;
        if (IS_O) {
            const float4 rv = *(const float4*)(resid + (size_t)row * D_DIM + col);
            cv.x += rv.x; cv.y += rv.y; cv.z += rv.z; cv.w += rv.w;
            *(float4*)(g_x + (size_t)row * D_DIM + col) = cv;
        } else {
            __nv_bfloat16* dst = (z == 0) ? g_q : (z == 1) ? g_k : g_v;
            const int bidx = row >> 11;
            const int sPos = row & 2047;
            const int hh = col >> 6;
            const int d = col & 63;
            uint2 p;
            p.x = packbf(cv.x, cv.y);
            p.y = packbf(cv.z, cv.w);
            *(uint2*)(dst + (((size_t)(bidx * NHEAD + hh) * S_LEN) + sPos) * HD + d) = p;
        }
    }
}

// ===========================================================================
// Flash attention v2: 4 warps x 32 q-rows; K/V fragments reused across the
// warp's two m16 blocks (halves ldmatrix traffic). Max-free log2 softmax,
// packed ex2, ones-MMA row sums. cp.async double-buffered KV, Q overlay.
// ===========================================================================
#define ATTN_SMEM_BYTES (2 * 18432)
#define ONESB 0x3F803F80u   // bf16x2 {1.0, 1.0}

__global__ __launch_bounds__(128, 3) void attn_k()
{
    extern __shared__ __nv_bfloat16 smh[];
    const uint32_t base = smem_u32(smh);
    const uint32_t qs_b = base;
    uint32_t ks_b[2], vs_b[2];
    ks_b[0] = base + 18432;
    vs_b[0] = base + 18432 + 9216;
    ks_b[1] = base;
    vs_b[1] = base + 9216;

    const int tid = threadIdx.x;
    const int lane = tid & 31;
    const int wid = tid >> 5;       // 0..3
    const int g = lane >> 2;
    const int t = lane & 3;

    const int bh = blockIdx.y;
    const int b = bh >> 4;
    const int h = bh & 15;
    const int q0 = blockIdx.x * 128;

    const __nv_bfloat16* qg = g_q + (size_t)bh * S_LEN * HD + (size_t)q0 * HD;
    const __nv_bfloat16* kg = g_k + (size_t)bh * S_LEN * HD;
    const __nv_bfloat16* vg = g_v + (size_t)bh * S_LEN * HD;

    // ---- prologue: async-load Q tile and KV tile 0 (128 threads) ----
#pragma unroll
    for (int j = 0; j < 8; j++) {
        const int lin = tid + j * 128;       // 1024 chunks of 16B
        const int r = lin >> 3;
        const int c8 = lin & 7;
        cp16(qs_b + r * 144 + c8 * 16, qg + r * 64 + c8 * 8);
    }
#pragma unroll
    for (int j = 0; j < 4; j++) {
        const int lin = tid + j * 128;       // 512 chunks
        const int r = lin >> 3;
        const int c8 = lin & 7;
        cp16(ks_b[0] + r * 144 + c8 * 16, kg + r * 64 + c8 * 8);
        cp16(vs_b[0] + r * 144 + c8 * 16, vg + r * 64 + c8 * 8);
    }
    CP_COMMIT();
    CP_WAIT0();
    __syncthreads();

    // ---- Q fragments pinned: 2 m-blocks x 4 k-steps ----
    const int wrow = wid * 32;
    uint32_t qa[2][4][4];
#pragma unroll
    for (int mblk = 0; mblk < 2; mblk++)
#pragma unroll
        for (int s = 0; s < 4; s++) {
            const uint32_t a = qs_b + (wrow + mblk * 16 + (lane & 15)) * 144
                             + ((lane >> 4) * 8 + s * 16) * 2;
            ldsm4(qa[mblk][s][0], qa[mblk][s][1], qa[mblk][s][2], qa[mblk][s][3], a);
        }
    __syncthreads();   // all warps done reading Q before X is overwritten

    float o[2][8][4];
#pragma unroll
    for (int mblk = 0; mblk < 2; mblk++)
#pragma unroll
        for (int nt = 0; nt < 8; nt++)
#pragma unroll
            for (int e = 0; e < 4; e++) o[mblk][nt][e] = 0.f;
    float lsum[2][4] = {{0.f, 0.f, 0.f, 0.f}, {0.f, 0.f, 0.f, 0.f}};

    const uint32_t* mbp[2][2];
#pragma unroll
    for (int mblk = 0; mblk < 2; mblk++) {
        const int r0 = q0 + wrow + mblk * 16 + g;
        mbp[mblk][0] = g_mbits + (size_t)(b * S_LEN + r0) * (S_LEN / 32);
        mbp[mblk][1] = g_mbits + (size_t)(b * S_LEN + r0 + 8) * (S_LEN / 32);
    }

    for (int t0 = 0; t0 < 32; t0++) {
        if (t0 + 1 < 32) {
            const int nb = (t0 + 1) & 1;
            const size_t off = (size_t)(t0 + 1) * 64 * 64;
#pragma unroll
            for (int j = 0; j < 4; j++) {
                const int lin = tid + j * 128;
                const int r = lin >> 3;
                const int c8 = lin & 7;
                cp16(ks_b[nb] + r * 144 + c8 * 16, kg + off + r * 64 + c8 * 8);
                cp16(vs_b[nb] + r * 144 + c8 * 16, vg + off + r * 64 + c8 * 8);
            }
            CP_COMMIT();
        }

        const uint32_t kb = ks_b[t0 & 1];
        const uint32_t vb = vs_b[t0 & 1];

        // mask words for this tile, pre-shifted by 2t
        const uint32_t t2 = 2 * t;
        uint32_t ms[2][2][2];
#pragma unroll
        for (int mblk = 0; mblk < 2; mblk++) {
            const uint2 a = *(const uint2*)(mbp[mblk][0] + t0 * 2);
            const uint2 c = *(const uint2*)(mbp[mblk][1] + t0 * 2);
            ms[mblk][0][0] = a.x >> t2;
            ms[mblk][0][1] = a.y >> t2;
            ms[mblk][1][0] = c.x >> t2;
            ms[mblk][1][1] = c.y >> t2;
        }

        // ---- S = Q K^T, mask, packed ex2; K frags shared by both m-blocks ----
        uint32_t pp[2][8][2];
#pragma unroll
        for (int nt = 0; nt < 8; nt++) {
            uint32_t kf[8];
            const uint32_t kaddr = kb + (nt * 8 + (lane & 7)) * 144 + (lane >> 3) * 16;
            ldsm4(kf[0], kf[1], kf[2], kf[3], kaddr);
            ldsm4(kf[4], kf[5], kf[6], kf[7], kaddr + 64);
            const uint32_t bit0 = 1u << ((nt & 3) * 8);
            const uint32_t bit1 = 2u << ((nt & 3) * 8);
#pragma unroll
            for (int mblk = 0; mblk < 2; mblk++) {
                float sacc[4] = {0.f, 0.f, 0.f, 0.f};
#pragma unroll
                for (int s = 0; s < 4; s++)
                    mma16(sacc, qa[mblk][s][0], qa[mblk][s][1],
                          qa[mblk][s][2], qa[mblk][s][3], kf[2 * s], kf[2 * s + 1]);
                const uint32_t w0 = ms[mblk][0][nt >> 2];
                const uint32_t w1 = ms[mblk][1][nt >> 2];
                const float v0 = (w0 & bit0) ? -130.f : sacc[0];
                const float v1 = (w0 & bit1) ? -130.f : sacc[1];
                const float v2 = (w1 & bit0) ? -130.f : sacc[2];
                const float v3 = (w1 & bit1) ? -130.f : sacc[3];
                pp[mblk][nt][0] = ex2bf2(packbf(v0, v1));
                pp[mblk][nt][1] = ex2bf2(packbf(v2, v3));
            }
        }

        // ---- O += P V ; l += P @ ones; V frags shared by both m-blocks ----
#pragma unroll
        for (int s = 0; s < 4; s++) {
            uint32_t a_[2][4];
#pragma unroll
            for (int mblk = 0; mblk < 2; mblk++) {
                a_[mblk][0] = pp[mblk][2 * s][0];
                a_[mblk][1] = pp[mblk][2 * s][1];
                a_[mblk][2] = pp[mblk][2 * s + 1][0];
                a_[mblk][3] = pp[mblk][2 * s + 1][1];
                mma16(lsum[mblk], a_[mblk][0], a_[mblk][1], a_[mblk][2], a_[mblk][3],
                      ONESB, ONESB);
            }
            const uint32_t vrow = s * 16 + ((lane >> 3) & 1) * 8 + (lane & 7);
#pragma unroll
            for (int np = 0; np < 4; np++) {
                uint32_t v0, v1, v2, v3;
                ldsm4t(v0, v1, v2, v3,
                       vb + vrow * 144 + (np * 2 + (lane >> 4)) * 16);
#pragma unroll
                for (int mblk = 0; mblk < 2; mblk++) {
                    mma16(o[mblk][np * 2],     a_[mblk][0], a_[mblk][1],
                          a_[mblk][2], a_[mblk][3], v0, v1);
                    mma16(o[mblk][np * 2 + 1], a_[mblk][0], a_[mblk][1],
                          a_[mblk][2], a_[mblk][3], v2, v3);
                }
            }
        }

        if (t0 + 1 < 32) {
            CP_WAIT0();
            __syncthreads();
        }
    }

    // ---- epilogue ----
#pragma unroll
    for (int mblk = 0; mblk < 2; mblk++) {
        const int row0 = q0 + wrow + mblk * 16 + g;
        const int row1 = row0 + 8;
        const float inv0 = 1.0f / lsum[mblk][0];
        const float inv1 = 1.0f / lsum[mblk][2];
#pragma unroll
        for (int nt = 0; nt < 8; nt++) {
            const int col = h * 64 + nt * 8 + 2 * t;
            *(uint32_t*)(g_ctx + (size_t)(b * S_LEN + row0) * D_DIM + col) =
                packbf(o[mblk][nt][0] * inv0, o[mblk][nt][1] * inv0);
            *(uint32_t*)(g_ctx + (size_t)(b * S_LEN + row1) * D_DIM + col) =
                packbf(o[mblk][nt][2] * inv1, o[mblk][nt][3] * inv1);
        }
    }
}

// ---------------------------------------------------------------------------
// LayerNorm over last dim (1024), one block per row.
// ---------------------------------------------------------------------------
__global__ __launch_bounds__(256) void ln_k(const float* __restrict__ gamma,
                                            const float* __restrict__ beta,
                                            float* __restrict__ out)
{
    const int row = blockIdx.x;
    const int t = threadIdx.x;
    const float* x = g_x + (size_t)row * D_DIM;
    float4 xv = *(const float4*)(x + t * 4);
    float s  = (xv.x + xv.y) + (xv.z + xv.w);
    float sq = xv.x * xv.x + xv.y * xv.y + xv.z * xv.z + xv.w * xv.w;
#pragma unroll
    for (int off = 16; off; off >>= 1) {
        s  += __shfl_xor_sync(0xffffffffu, s, off);
        sq += __shfl_xor_sync(0xffffffffu, sq, off);
    }
    __shared__ float sh[16];
    const int w = t >> 5;
    if ((t & 31) == 0) { sh[w] = s; sh[8 + w] = sq; }
    __syncthreads();
    float st = 0.f, sqt = 0.f;
#pragma unroll
    for (int i = 0; i < 8; i++) { st += sh[i]; sqt += sh[8 + i]; }
    const float mu   = st * (1.0f / D_DIM);
    const float var  = sqt * (1.0f / D_DIM) - mu * mu;
    const float rstd = rsqrtf(var + 1e-5f);
    float4 g4 = *(const float4*)(gamma + t * 4);
    float4 b4 = *(const float4*)(beta + t * 4);
    float4 o;
    o.x = (xv.x - mu) * rstd * g4.x + b4.x;
    o.y = (xv.y - mu) * rstd * g4.y + b4.y;
    o.z = (xv.z - mu) * rstd * g4.z + b4.z;
    o.w = (xv.w - mu) * rstd * g4.w + b4.w;
    *(float4*)(out + (size_t)row * D_DIM + t * 4) = o;
}

// ---------------------------------------------------------------------------
extern "C" void kernel_launch(void* const* d_in, const int* in_sizes, int n_in,
                              void* d_out, int out_size)
{
    const float* Q   = (const float*)d_in[0];
    const float* Kin = (const float*)d_in[1];
    const float* V   = (const float*)d_in[2];
    const int*   mask = (const int*)d_in[3];
    const float* Wq = (const float*)d_in[4];
    const float* bq = (const float*)d_in[5];
    const float* Wk = (const float*)d_in[6];
    const float* bk = (const float*)d_in[7];
    const float* Wv = (const float*)d_in[8];
    const float* bv = (const float*)d_in[9];
    const float* Wo = (const float*)d_in[10];
    const float* bo = (const float*)d_in[11];
    const float* gamma = (const float*)d_in[12];
    const float* beta  = (const float*)d_in[13];
    float* out = (float*)d_out;

    cudaFuncSetAttribute(attn_k, cudaFuncAttributeMaxDynamicSharedMemorySize, ATTN_SMEM_BYTES);
    cudaFuncSetAttribute(mm2_k<0>, cudaFuncAttributeMaxDynamicSharedMemorySize, MM_SMEM_BYTES);
    cudaFuncSetAttribute(mm2_k<1>, cudaFuncAttributeMaxDynamicSharedMemorySize, MM_SMEM_BYTES);

    cvt_k<<<dim3(4096, 7), 256>>>(Q, Kin, V, Wq, Wk, Wv, Wo);
    mb_k<<<2 * S_LEN, 256>>>(mask);

    mm2_k<0><<<dim3(8, 32, 3), 256, MM_SMEM_BYTES>>>(bq, bk, bv, nullptr);
    attn_k<<<dim3(16, 32), 128, ATTN_SMEM_BYTES>>>();
    mm2_k<1><<<dim3(8, 32, 1), 256, MM_SMEM_BYTES>>>(bo, nullptr, nullptr, Q);
    ln_k<<<4096, 256>>>(gamma, beta, out);
}

// round 13
// speedup vs baseline: 1.0156x; 1.0156x over previous
#include <cuda_runtime.h>
#include <cuda_bf16.h>
#include <mma.h>
#include <math.h>
#include <cstdint>

using namespace nvcuda;

#define S_LEN 2048
#define D_DIM 1024
#define NHEAD 16
#define HD 64
#define MROWS 4096
// 0.125 (1/sqrt(64)) * log2(e), folded into the Q projection epilogue
#define QSCALE 0.1803368801111244f

// Scratch (device globals: no allocations allowed)
__device__ __nv_bfloat16 g_q[MROWS * D_DIM];    // [b,h,s,d] bf16, pre-scaled
__device__ __nv_bfloat16 g_k[MROWS * D_DIM];    // [b,h,s,d] bf16
__device__ __nv_bfloat16 g_v[MROWS * D_DIM];    // [b,h,s,d] bf16
__device__ __nv_bfloat16 g_ctx[MROWS * D_DIM];  // [b,s,h*64+d] bf16
__device__ float g_x[MROWS * D_DIM];            // pre-LN fp32
__device__ uint32_t g_mbits[2 * S_LEN * (S_LEN / 32)];  // packed mask bits
// bf16 copies of inputs & weights (cvt once, consumed by cp.async GEMMs)
__device__ __nv_bfloat16 g_qin[MROWS * D_DIM];
__device__ __nv_bfloat16 g_kin[MROWS * D_DIM];
__device__ __nv_bfloat16 g_vin[MROWS * D_DIM];
__device__ __nv_bfloat16 g_wbf[4 * D_DIM * D_DIM];

// ---------------------------------------------------------------------------
// helpers
// ---------------------------------------------------------------------------
__device__ __forceinline__ uint32_t smem_u32(const void* p) {
    return (uint32_t)__cvta_generic_to_shared(p);
}
__device__ __forceinline__ void cp16(uint32_t dst, const void* src) {
    asm volatile("cp.async.cg.shared.global [%0], [%1], 16;"
                 :: "r"(dst), "l"(src) : "memory");
}
#define CP_COMMIT() asm volatile("cp.async.commit_group;" ::: "memory")
#define CP_WAIT0()  asm volatile("cp.async.wait_group 0;" ::: "memory")
#define CP_WAIT1()  asm volatile("cp.async.wait_group 1;" ::: "memory")

__device__ __forceinline__ void ldsm4(uint32_t& r0, uint32_t& r1,
                                      uint32_t& r2, uint32_t& r3, uint32_t a) {
    asm volatile("ldmatrix.sync.aligned.m8n8.x4.shared.b16 {%0,%1,%2,%3}, [%4];"
                 : "=r"(r0), "=r"(r1), "=r"(r2), "=r"(r3) : "r"(a));
}
__device__ __forceinline__ void ldsm4t(uint32_t& r0, uint32_t& r1,
                                       uint32_t& r2, uint32_t& r3, uint32_t a) {
    asm volatile("ldmatrix.sync.aligned.m8n8.x4.trans.shared.b16 {%0,%1,%2,%3}, [%4];"
                 : "=r"(r0), "=r"(r1), "=r"(r2), "=r"(r3) : "r"(a));
}
// D(16x8,f32) += A(16x16,bf16) * B(16x8,bf16)
__device__ __forceinline__ void mma16(float* d, uint32_t a0, uint32_t a1,
                                      uint32_t a2, uint32_t a3,
                                      uint32_t b0, uint32_t b1) {
    asm volatile(
        "mma.sync.aligned.m16n8k16.row.col.f32.bf16.bf16.f32 "
        "{%0,%1,%2,%3}, {%4,%5,%6,%7}, {%8,%9}, {%0,%1,%2,%3};"
        : "+f"(d[0]), "+f"(d[1]), "+f"(d[2]), "+f"(d[3])
        : "r"(a0), "r"(a1), "r"(a2), "r"(a3), "r"(b0), "r"(b1));
}
// pack two floats -> bf16x2 (lo in low 16 bits)
__device__ __forceinline__ uint32_t packbf(float lo, float hi) {
    uint32_t r;
    asm("cvt.rn.bf16x2.f32 %0, %1, %2;" : "=r"(r) : "f"(hi), "f"(lo));
    return r;
}
// packed 2^x on bf16x2 (subnormal results flushed to 0)
__device__ __forceinline__ uint32_t ex2bf2(uint32_t x) {
    uint32_t r;
    asm("ex2.approx.ftz.bf16x2 %0, %1;" : "=r"(r) : "r"(x));
    return r;
}

// ===========================================================================
// cvt: fp32 -> bf16 copies. z 0..2: Q/K/V inputs (4M elems); 3..6: weights (1M)
// ===========================================================================
__global__ __launch_bounds__(256) void cvt_k(
    const float* __restrict__ Q, const float* __restrict__ K,
    const float* __restrict__ V,
    const float* __restrict__ Wq, const float* __restrict__ Wk,
    const float* __restrict__ Wv, const float* __restrict__ Wo)
{
    const int z = blockIdx.y;
    const float* src;
    __nv_bfloat16* dst;
    int n4;
    if (z < 3) {
        src = (z == 0) ? Q : (z == 1) ? K : V;
        dst = (z == 0) ? g_qin : (z == 1) ? g_kin : g_vin;
        n4 = (MROWS * D_DIM) / 4;
    } else {
        src = (z == 3) ? Wq : (z == 4) ? Wk : (z == 5) ? Wv : Wo;
        dst = g_wbf + (size_t)(z - 3) * (D_DIM * D_DIM);
        n4 = (D_DIM * D_DIM) / 4;
    }
    const int idx = blockIdx.x * 256 + threadIdx.x;
    if (idx >= n4) return;
    const float4 v = ((const float4*)src)[idx];
    uint2 p;
    p.x = packbf(v.x, v.y);
    p.y = packbf(v.z, v.w);
    ((uint2*)dst)[idx] = p;
}

// ===========================================================================
// Mask bit-pack: g_mbits[b*2048+row][word] = ballot of mask[row][word*32+lane]
// ===========================================================================
__global__ __launch_bounds__(256) void mb_k(const int* __restrict__ mask)
{
    const int rr = blockIdx.x;
    const int w = threadIdx.x >> 5;
    const int lane = threadIdx.x & 31;
    const int* mrow = mask + (size_t)rr * S_LEN;
    uint32_t* obase = g_mbits + (size_t)rr * (S_LEN / 32);
#pragma unroll
    for (int i = 0; i < 8; i++) {
        const int word = w + i * 8;
        const uint32_t bal =
            __ballot_sync(0xffffffffu, mrow[word * 32 + lane] != 0);
        if (lane == 0) obase[word] = bal;
    }
}

// ===========================================================================
// bf16 GEMM, cp.async double-buffered (proven R8-R10 version):
// C[4096x1024] = A @ W + bias. CTA 128x128, K-chunk 64, 8 warps of 32x64.
// IS_O=0: blockIdx.z selects Q/K/V projection; Q result pre-scaled by QSCALE.
// IS_O=1: A=g_ctx, += fp32 resid -> g_x.
// smem bytes: A0[0,18432) A1[18432,36864) B0[36864,54272) B1[54272,71680)
// ===========================================================================
#define MM_SMEM_BYTES (35840 * 2)

template <int IS_O>
__global__ __launch_bounds__(256, 2) void mm2_k(
    const float* __restrict__ b0p, const float* __restrict__ b1p,
    const float* __restrict__ b2p, const float* __restrict__ resid)
{
    extern __shared__ __nv_bfloat16 smh[];
    const uint32_t sb = smem_u32(smh);
    const uint32_t as_b[2] = {sb, sb + 18432};
    const uint32_t bs_b[2] = {sb + 36864, sb + 36864 + 17408};
    float* Cs = (float*)smh;

    const int tid = threadIdx.x;
    const int wid = tid >> 5;
    const int wm0 = (wid & 3) * 32;
    const int wn0 = (wid >> 2) * 64;
    const int brow = blockIdx.y * 128;
    const int bcol = blockIdx.x * 128;
    const int z = IS_O ? 3 : blockIdx.z;

    const __nv_bfloat16* A =
        IS_O ? g_ctx : (z == 0) ? g_qin : (z == 1) ? g_kin : g_vin;
    const __nv_bfloat16* W = g_wbf + (size_t)z * (D_DIM * D_DIM);
    const float* bias = IS_O ? b0p : (z == 0) ? b0p : (z == 1) ? b1p : b2p;

    const int ar = tid >> 1;
    const int ac = (tid & 1) * 4;
    const int br_ = tid >> 2;
    const int bc_ = (tid & 3) * 4;

    auto issueA = [&](int buf, int kc) {
        const __nv_bfloat16* srcr = A + (size_t)(brow + ar) * D_DIM + kc * 64;
        const uint32_t dstr = as_b[buf] + ar * 144;
#pragma unroll
        for (int c = 0; c < 4; c++)
            cp16(dstr + (ac + c) * 16, srcr + (ac + c) * 8);
    };
    auto issueB = [&](int buf, int kc) {
        const __nv_bfloat16* srcr = W + (size_t)(kc * 64 + br_) * D_DIM + bcol;
        const uint32_t dstr = bs_b[buf] + br_ * 272;
#pragma unroll
        for (int c = 0; c < 4; c++)
            cp16(dstr + (bc_ + c) * 16, srcr + (bc_ + c) * 8);
    };

    wmma::fragment<wmma::accumulator, 16, 16, 16, float> acc[2][4];
#pragma unroll
    for (int mi = 0; mi < 2; mi++)
#pragma unroll
        for (int ni = 0; ni < 4; ni++)
            wmma::fill_fragment(acc[mi][ni], 0.0f);

    issueA(0, 0);
    issueB(0, 0);
    CP_COMMIT();

    for (int kc = 0; kc < 16; kc++) {
        const int buf = kc & 1;
        if (kc + 1 < 16) {
            issueA(buf ^ 1, kc + 1);
            issueB(buf ^ 1, kc + 1);
            CP_COMMIT();
            CP_WAIT1();
        } else {
            CP_WAIT0();
        }
        __syncthreads();

        const __nv_bfloat16* As = smh + buf * 9216;           // elements
        const __nv_bfloat16* Bs = smh + 18432 + buf * 8704;   // elements
#pragma unroll
        for (int k0 = 0; k0 < 64; k0 += 16) {
            wmma::fragment<wmma::matrix_a, 16, 16, 16, __nv_bfloat16,
                           wmma::row_major> af[2];
            wmma::fragment<wmma::matrix_b, 16, 16, 16, __nv_bfloat16,
                           wmma::row_major> bf[4];
#pragma unroll
            for (int mi = 0; mi < 2; mi++)
                wmma::load_matrix_sync(af[mi], &As[(wm0 + mi * 16) * 72 + k0], 72);
#pragma unroll
            for (int ni = 0; ni < 4; ni++)
                wmma::load_matrix_sync(bf[ni], &Bs[k0 * 136 + wn0 + ni * 16], 136);
#pragma unroll
            for (int mi = 0; mi < 2; mi++)
#pragma unroll
                for (int ni = 0; ni < 4; ni++)
                    wmma::mma_sync(acc[mi][ni], af[mi], bf[ni], acc[mi][ni]);
        }
        __syncthreads();   // readers done before next prefetch overwrites buf
    }

#pragma unroll
    for (int mi = 0; mi < 2; mi++)
#pragma unroll
        for (int ni = 0; ni < 4; ni++)
            wmma::store_matrix_sync(&Cs[(wm0 + mi * 16) * 136 + wn0 + ni * 16],
                                    acc[mi][ni], 136, wmma::mem_row_major);
    __syncthreads();

    const float oscale = (!IS_O && z == 0) ? QSCALE : 1.0f;
#pragma unroll
    for (int j = 0; j < 16; j++) {
        const int lin = tid + j * 256;
        const int r = lin >> 5;
        const int c4 = (lin & 31) << 2;
        const int row = brow + r;
        const int col = bcol + c4;
        float4 cv = *(float4*)&Cs[r * 136 + c4];
        const float4 bi = *(const float4*)(bias + col);
        cv.x = (cv.x + bi.x) * oscale;
        cv.y = (cv.y + bi.y) * oscale;
        cv.z = (cv.z + bi.z) * oscale;
        cv.w = (cv.w + bi.w) * oscale;
        if (IS_O) {
            const float4 rv = *(const float4*)(resid + (size_t)row * D_DIM + col);
            cv.x += rv.x; cv.y += rv.y; cv.z += rv.z; cv.w += rv.w;
            *(float4*)(g_x + (size_t)row * D_DIM + col) = cv;
        } else {
            __nv_bfloat16* dst = (z == 0) ? g_q : (z == 1) ? g_k : g_v;
            const int bidx = row >> 11;
            const int sPos = row & 2047;
            const int hh = col >> 6;
            const int d = col & 63;
            uint2 p;
            p.x = packbf(cv.x, cv.y);
            p.y = packbf(cv.z, cv.w);
            *(uint2*)(dst + (((size_t)(bidx * NHEAD + hh) * S_LEN) + sPos) * HD + d) = p;
        }
    }
}

// ===========================================================================
// Flash attention (R10 structure, 128-key KV tiles): 8 warps x 16 q-rows,
// 256 threads, 2 CTAs/SM. Max-free log2 softmax, packed bf16x2 ex2, ones-MMA
// row sums, cp.async double-buffered 128-key KV tiles (16 loop iterations).
// smem (flat, no aliasing): Q[0,18432) K0[18432) V0[36864) K1[55296) V1[73728)
// ===========================================================================
#define ATTN_SMEM_BYTES 92160
#define ONESB 0x3F803F80u   // bf16x2 {1.0, 1.0}

__global__ __launch_bounds__(256, 2) void attn_k()
{
    extern __shared__ __nv_bfloat16 smh[];
    const uint32_t base = smem_u32(smh);
    const uint32_t qs_b = base;
    uint32_t ks_b[2], vs_b[2];
    ks_b[0] = base + 18432;
    vs_b[0] = base + 36864;
    ks_b[1] = base + 55296;
    vs_b[1] = base + 73728;

    const int tid = threadIdx.x;
    const int lane = tid & 31;
    const int wid = tid >> 5;
    const int g = lane >> 2;
    const int t = lane & 3;

    const int bh = blockIdx.y;
    const int b = bh >> 4;
    const int h = bh & 15;
    const int q0 = blockIdx.x * 128;

    const __nv_bfloat16* qg = g_q + (size_t)bh * S_LEN * HD + (size_t)q0 * HD;
    const __nv_bfloat16* kg = g_k + (size_t)bh * S_LEN * HD;
    const __nv_bfloat16* vg = g_v + (size_t)bh * S_LEN * HD;

    // ---- prologue: async-load Q tile (128x64) and KV tile 0 (128 keys) ----
#pragma unroll
    for (int j = 0; j < 4; j++) {
        const int lin = tid + j * 256;       // 1024 chunks of 16B
        const int r = lin >> 3;
        const int c8 = lin & 7;
        cp16(qs_b + r * 144 + c8 * 16, qg + r * 64 + c8 * 8);
        cp16(ks_b[0] + r * 144 + c8 * 16, kg + r * 64 + c8 * 8);
        cp16(vs_b[0] + r * 144 + c8 * 16, vg + r * 64 + c8 * 8);
    }
    CP_COMMIT();
    CP_WAIT0();
    __syncthreads();

    // ---- Q fragments pinned: 4 k-steps x 4 regs ----
    const int wrow = wid * 16;
    uint32_t qa[4][4];
#pragma unroll
    for (int s = 0; s < 4; s++) {
        const uint32_t a = qs_b + (wrow + (lane & 15)) * 144
                         + ((lane >> 4) * 8 + s * 16) * 2;
        ldsm4(qa[s][0], qa[s][1], qa[s][2], qa[s][3], a);
    }

    float o[8][4];
#pragma unroll
    for (int nt = 0; nt < 8; nt++)
#pragma unroll
        for (int e = 0; e < 4; e++) o[nt][e] = 0.f;
    float lsum[4] = {0.f, 0.f, 0.f, 0.f};   // ones-B MMA accumulator: row sums

    const int row0 = q0 + wrow + g;
    const int row1 = row0 + 8;
    const uint32_t* mb0 = g_mbits + (size_t)(b * S_LEN + row0) * (S_LEN / 32);
    const uint32_t* mb1 = g_mbits + (size_t)(b * S_LEN + row1) * (S_LEN / 32);

    for (int t0 = 0; t0 < 16; t0++) {
        // issue next 128-key KV tile into the other buffer
        if (t0 + 1 < 16) {
            const int nb = (t0 + 1) & 1;
            const size_t off = (size_t)(t0 + 1) * 128 * 64;
#pragma unroll
            for (int j = 0; j < 4; j++) {
                const int lin = tid + j * 256;
                const int r = lin >> 3;
                const int c8 = lin & 7;
                cp16(ks_b[nb] + r * 144 + c8 * 16, kg + off + r * 64 + c8 * 8);
                cp16(vs_b[nb] + r * 144 + c8 * 16, vg + off + r * 64 + c8 * 8);
            }
            CP_COMMIT();
        }

        const uint32_t kb = ks_b[t0 & 1];
        const uint32_t vb = vs_b[t0 & 1];

        // mask words for this tile (128 keys = 4 words/row), pre-shifted by 2t
        const uint32_t t2 = 2 * t;
        const uint4 ma = *(const uint4*)(mb0 + t0 * 4);
        const uint4 mc = *(const uint4*)(mb1 + t0 * 4);
        const uint32_t m0w[4] = {ma.x >> t2, ma.y >> t2, ma.z >> t2, ma.w >> t2};
        const uint32_t m1w[4] = {mc.x >> t2, mc.y >> t2, mc.z >> t2, mc.w >> t2};

        // ---- S = Q K^T, mask, packed ex2 over 16 n-tiles ----
        uint32_t pp[16][2];
#pragma unroll
        for (int nt = 0; nt < 16; nt++) {
            float sacc[4] = {0.f, 0.f, 0.f, 0.f};
            uint32_t kf[8];
            const uint32_t kaddr = kb + (nt * 8 + (lane & 7)) * 144 + (lane >> 3) * 16;
            ldsm4(kf[0], kf[1], kf[2], kf[3], kaddr);
            ldsm4(kf[4], kf[5], kf[6], kf[7], kaddr + 64);
#pragma unroll
            for (int s = 0; s < 4; s++)
                mma16(sacc, qa[s][0], qa[s][1], qa[s][2], qa[s][3],
                      kf[2 * s], kf[2 * s + 1]);
            const uint32_t w0 = m0w[nt >> 2];
            const uint32_t w1 = m1w[nt >> 2];
            const uint32_t bit0 = 1u << ((nt & 3) * 8);
            const uint32_t bit1 = 2u << ((nt & 3) * 8);
            const float v0 = (w0 & bit0) ? -130.f : sacc[0];
            const float v1 = (w0 & bit1) ? -130.f : sacc[1];
            const float v2 = (w1 & bit0) ? -130.f : sacc[2];
            const float v3 = (w1 & bit1) ? -130.f : sacc[3];
            pp[nt][0] = ex2bf2(packbf(v0, v1));
            pp[nt][1] = ex2bf2(packbf(v2, v3));
        }

        // ---- O += P V ; l += P @ ones; 8 k-steps over 128 keys ----
#pragma unroll
        for (int s = 0; s < 8; s++) {
            const uint32_t a0 = pp[2 * s][0];
            const uint32_t a1 = pp[2 * s][1];
            const uint32_t a2 = pp[2 * s + 1][0];
            const uint32_t a3 = pp[2 * s + 1][1];
            mma16(lsum, a0, a1, a2, a3, ONESB, ONESB);
            const uint32_t vrow = s * 16 + ((lane >> 3) & 1) * 8 + (lane & 7);
#pragma unroll
            for (int np = 0; np < 4; np++) {
                uint32_t v0, v1, v2, v3;
                ldsm4t(v0, v1, v2, v3,
                       vb + vrow * 144 + (np * 2 + (lane >> 4)) * 16);
                mma16(o[np * 2],     a0, a1, a2, a3, v0, v1);
                mma16(o[np * 2 + 1], a0, a1, a2, a3, v2, v3);
            }
        }

        if (t0 + 1 < 16) {
            CP_WAIT0();
            __syncthreads();
        }
    }

    // every column of lsum equals the row sum: no shuffles needed
    const float inv0 = 1.0f / lsum[0];
    const float inv1 = 1.0f / lsum[2];
#pragma unroll
    for (int nt = 0; nt < 8; nt++) {
        const int col = h * 64 + nt * 8 + 2 * t;
        *(uint32_t*)(g_ctx + (size_t)(b * S_LEN + row0) * D_DIM + col) =
            packbf(o[nt][0] * inv0, o[nt][1] * inv0);
        *(uint32_t*)(g_ctx + (size_t)(b * S_LEN + row1) * D_DIM + col) =
            packbf(o[nt][2] * inv1, o[nt][3] * inv1);
    }
}

// ---------------------------------------------------------------------------
// LayerNorm over last dim (1024), one block per row.
// ---------------------------------------------------------------------------
__global__ __launch_bounds__(256) void ln_k(const float* __restrict__ gamma,
                                            const float* __restrict__ beta,
                                            float* __restrict__ out)
{
    const int row = blockIdx.x;
    const int t = threadIdx.x;
    const float* x = g_x + (size_t)row * D_DIM;
    float4 xv = *(const float4*)(x + t * 4);
    float s  = (xv.x + xv.y) + (xv.z + xv.w);
    float sq = xv.x * xv.x + xv.y * xv.y + xv.z * xv.z + xv.w * xv.w;
#pragma unroll
    for (int off = 16; off; off >>= 1) {
        s  += __shfl_xor_sync(0xffffffffu, s, off);
        sq += __shfl_xor_sync(0xffffffffu, sq, off);
    }
    __shared__ float sh[16];
    const int w = t >> 5;
    if ((t & 31) == 0) { sh[w] = s; sh[8 + w] = sq; }
    __syncthreads();
    float st = 0.f, sqt = 0.f;
#pragma unroll
    for (int i = 0; i < 8; i++) { st += sh[i]; sqt += sh[8 + i]; }
    const float mu   = st * (1.0f / D_DIM);
    const float var  = sqt * (1.0f / D_DIM) - mu * mu;
    const float rstd = rsqrtf(var + 1e-5f);
    float4 g4 = *(const float4*)(gamma + t * 4);
    float4 b4 = *(const float4*)(beta + t * 4);
    float4 o;
    o.x = (xv.x - mu) * rstd * g4.x + b4.x;
    o.y = (xv.y - mu) * rstd * g4.y + b4.y;
    o.z = (xv.z - mu) * rstd * g4.z + b4.z;
    o.w = (xv.w - mu) * rstd * g4.w + b4.w;
    *(float4*)(out + (size_t)row * D_DIM + t * 4) = o;
}

// ---------------------------------------------------------------------------
extern "C" void kernel_launch(void* const* d_in, const int* in_sizes, int n_in,
                              void* d_out, int out_size)
{
    const float* Q   = (const float*)d_in[0];
    const float* Kin = (const float*)d_in[1];
    const float* V   = (const float*)d_in[2];
    const int*   mask = (const int*)d_in[3];
    const float* Wq = (const float*)d_in[4];
    const float* bq = (const float*)d_in[5];
    const float* Wk = (const float*)d_in[6];
    const float* bk = (const float*)d_in[7];
    const float* Wv = (const float*)d_in[8];
    const float* bv = (const float*)d_in[9];
    const float* Wo = (const float*)d_in[10];
    const float* bo = (const float*)d_in[11];
    const float* gamma = (const float*)d_in[12];
    const float* beta  = (const float*)d_in[13];
    float* out = (float*)d_out;

    cudaFuncSetAttribute(attn_k, cudaFuncAttributeMaxDynamicSharedMemorySize, ATTN_SMEM_BYTES);
    cudaFuncSetAttribute(mm2_k<0>, cudaFuncAttributeMaxDynamicSharedMemorySize, MM_SMEM_BYTES);
    cudaFuncSetAttribute(mm2_k<1>, cudaFuncAttributeMaxDynamicSharedMemorySize, MM_SMEM_BYTES);

    cvt_k<<<dim3(4096, 7), 256>>>(Q, Kin, V, Wq, Wk, Wv, Wo);
    mb_k<<<2 * S_LEN, 256>>>(mask);

    mm2_k<0><<<dim3(8, 32, 3), 256, MM_SMEM_BYTES>>>(bq, bk, bv, nullptr);
    attn_k<<<dim3(16, 32), 256, ATTN_SMEM_BYTES>>>();
    mm2_k<1><<<dim3(8, 32, 1), 256, MM_SMEM_BYTES>>>(bo, nullptr, nullptr, Q);
    ln_k<<<4096, 256>>>(gamma, beta, out);
}

// round 14
// speedup vs baseline: 1.1438x; 1.1262x over previous
#include <cuda_runtime.h>
#include <cuda_bf16.h>
#include <math.h>
#include <cstdint>

#define S_LEN 2048
#define D_DIM 1024
#define NHEAD 16
#define HD 64
#define MROWS 4096
// 0.125 (1/sqrt(64)) * log2(e), folded into the Q projection epilogue
#define QSCALE 0.1803368801111244f

// Scratch (device globals: no allocations allowed)
__device__ __nv_bfloat16 g_q[MROWS * D_DIM];    // [b,h,s,d] bf16, pre-scaled
__device__ __nv_bfloat16 g_k[MROWS * D_DIM];    // [b,h,s,d] bf16
__device__ __nv_bfloat16 g_v[MROWS * D_DIM];    // [b,h,s,d] bf16
__device__ __nv_bfloat16 g_ctx[MROWS * D_DIM];  // [b,s,h*64+d] bf16
__device__ float g_x[MROWS * D_DIM];            // pre-LN fp32
__device__ uint32_t g_mbits[2 * S_LEN * (S_LEN / 32)];  // packed mask bits
// bf16 copies of inputs & weights (cvt once, consumed by cp.async GEMMs)
__device__ __nv_bfloat16 g_qin[MROWS * D_DIM];
__device__ __nv_bfloat16 g_kin[MROWS * D_DIM];
__device__ __nv_bfloat16 g_vin[MROWS * D_DIM];
__device__ __nv_bfloat16 g_wbf[4 * D_DIM * D_DIM];

// ---------------------------------------------------------------------------
// helpers
// ---------------------------------------------------------------------------
__device__ __forceinline__ uint32_t smem_u32(const void* p) {
    return (uint32_t)__cvta_generic_to_shared(p);
}
__device__ __forceinline__ void cp16(uint32_t dst, const void* src) {
    asm volatile("cp.async.cg.shared.global [%0], [%1], 16;"
                 :: "r"(dst), "l"(src) : "memory");
}
#define CP_COMMIT() asm volatile("cp.async.commit_group;" ::: "memory")
#define CP_WAIT0()  asm volatile("cp.async.wait_group 0;" ::: "memory")
#define CP_WAIT1()  asm volatile("cp.async.wait_group 1;" ::: "memory")

__device__ __forceinline__ void ldsm4(uint32_t& r0, uint32_t& r1,
                                      uint32_t& r2, uint32_t& r3, uint32_t a) {
    asm volatile("ldmatrix.sync.aligned.m8n8.x4.shared.b16 {%0,%1,%2,%3}, [%4];"
                 : "=r"(r0), "=r"(r1), "=r"(r2), "=r"(r3) : "r"(a));
}
__device__ __forceinline__ void ldsm4t(uint32_t& r0, uint32_t& r1,
                                       uint32_t& r2, uint32_t& r3, uint32_t a) {
    asm volatile("ldmatrix.sync.aligned.m8n8.x4.trans.shared.b16 {%0,%1,%2,%3}, [%4];"
                 : "=r"(r0), "=r"(r1), "=r"(r2), "=r"(r3) : "r"(a));
}
// D(16x8,f32) += A(16x16,bf16) * B(16x8,bf16)
__device__ __forceinline__ void mma16(float* d, uint32_t a0, uint32_t a1,
                                      uint32_t a2, uint32_t a3,
                                      uint32_t b0, uint32_t b1) {
    asm volatile(
        "mma.sync.aligned.m16n8k16.row.col.f32.bf16.bf16.f32 "
        "{%0,%1,%2,%3}, {%4,%5,%6,%7}, {%8,%9}, {%0,%1,%2,%3};"
        : "+f"(d[0]), "+f"(d[1]), "+f"(d[2]), "+f"(d[3])
        : "r"(a0), "r"(a1), "r"(a2), "r"(a3), "r"(b0), "r"(b1));
}
// pack two floats -> bf16x2 (lo in low 16 bits)
__device__ __forceinline__ uint32_t packbf(float lo, float hi) {
    uint32_t r;
    asm("cvt.rn.bf16x2.f32 %0, %1, %2;" : "=r"(r) : "f"(hi), "f"(lo));
    return r;
}
// packed 2^x on bf16x2 (subnormal results flushed to 0)
__device__ __forceinline__ uint32_t ex2bf2(uint32_t x) {
    uint32_t r;
    asm("ex2.approx.ftz.bf16x2 %0, %1;" : "=r"(r) : "r"(x));
    return r;
}

// ===========================================================================
// cvt: fp32 -> bf16 copies. z 0..2: Q/K/V inputs (4M elems); 3..6: weights (1M)
// ===========================================================================
__global__ __launch_bounds__(256) void cvt_k(
    const float* __restrict__ Q, const float* __restrict__ K,
    const float* __restrict__ V,
    const float* __restrict__ Wq, const float* __restrict__ Wk,
    const float* __restrict__ Wv, const float* __restrict__ Wo)
{
    const int z = blockIdx.y;
    const float* src;
    __nv_bfloat16* dst;
    int n4;
    if (z < 3) {
        src = (z == 0) ? Q : (z == 1) ? K : V;
        dst = (z == 0) ? g_qin : (z == 1) ? g_kin : g_vin;
        n4 = (MROWS * D_DIM) / 4;
    } else {
        src = (z == 3) ? Wq : (z == 4) ? Wk : (z == 5) ? Wv : Wo;
        dst = g_wbf + (size_t)(z - 3) * (D_DIM * D_DIM);
        n4 = (D_DIM * D_DIM) / 4;
    }
    const int idx = blockIdx.x * 256 + threadIdx.x;
    if (idx >= n4) return;
    const float4 v = ((const float4*)src)[idx];
    uint2 p;
    p.x = packbf(v.x, v.y);
    p.y = packbf(v.z, v.w);
    ((uint2*)dst)[idx] = p;
}

// ===========================================================================
// Mask bit-pack: g_mbits[b*2048+row][word] = ballot of mask[row][word*32+lane]
// ===========================================================================
__global__ __launch_bounds__(256) void mb_k(const int* __restrict__ mask)
{
    const int rr = blockIdx.x;
    const int w = threadIdx.x >> 5;
    const int lane = threadIdx.x & 31;
    const int* mrow = mask + (size_t)rr * S_LEN;
    uint32_t* obase = g_mbits + (size_t)rr * (S_LEN / 32);
#pragma unroll
    for (int i = 0; i < 8; i++) {
        const int word = w + i * 8;
        const uint32_t bal =
            __ballot_sync(0xffffffffu, mrow[word * 32 + lane] != 0);
        if (lane == 0) obase[word] = bal;
    }
}

// ===========================================================================
// bf16 GEMM, raw mma + ldsm (attn-style), cp.async double-buffered.
// C[4096x1024] = A @ W + bias. CTA 128x128, K-chunk 64, 8 warps of 32x64.
// Epilogue writes straight from accumulator registers (no smem round-trip).
// IS_O=0: blockIdx.z selects Q/K/V projection; Q result pre-scaled by QSCALE.
// IS_O=1: A=g_ctx, += fp32 resid -> g_x.
// smem bytes: A0[0,18432) A1[18432,36864) B0[36864,54272) B1[54272,71680)
// A row stride 144 B (64 data + pad); B row stride 272 B (128 data + pad).
// ===========================================================================
#define MM_SMEM_BYTES 71680

template <int IS_O>
__global__ __launch_bounds__(256, 2) void mm3_k(
    const float* __restrict__ b0p, const float* __restrict__ b1p,
    const float* __restrict__ b2p, const float* __restrict__ resid)
{
    extern __shared__ __nv_bfloat16 smh[];
    const uint32_t sb = smem_u32(smh);
    const uint32_t as_b[2] = {sb, sb + 18432};
    const uint32_t bs_b[2] = {sb + 36864, sb + 36864 + 17408};

    const int tid = threadIdx.x;
    const int lane = tid & 31;
    const int wid = tid >> 5;
    const int g = lane >> 2;
    const int t = lane & 3;
    const int wm0 = (wid & 3) * 32;           // warp m offset (row)
    const int wn0 = (wid >> 2) * 64;          // warp n offset (col)
    const int wnc = (wid >> 2) * 8;           // warp n offset in 16B chunks
    const int brow = blockIdx.y * 128;
    const int bcol = blockIdx.x * 128;
    const int z = IS_O ? 3 : blockIdx.z;

    const __nv_bfloat16* A =
        IS_O ? g_ctx : (z == 0) ? g_qin : (z == 1) ? g_kin : g_vin;
    const __nv_bfloat16* W = g_wbf + (size_t)z * (D_DIM * D_DIM);
    const float* bias = IS_O ? b0p : (z == 0) ? b0p : (z == 1) ? b1p : b2p;

    const int ar = tid >> 1;
    const int ac = (tid & 1) * 4;
    const int br_ = tid >> 2;
    const int bc_ = (tid & 3) * 4;

    auto issueA = [&](int buf, int kc) {
        const __nv_bfloat16* srcr = A + (size_t)(brow + ar) * D_DIM + kc * 64;
        const uint32_t dstr = as_b[buf] + ar * 144;
#pragma unroll
        for (int c = 0; c < 4; c++)
            cp16(dstr + (ac + c) * 16, srcr + (ac + c) * 8);
    };
    auto issueB = [&](int buf, int kc) {
        const __nv_bfloat16* srcr = W + (size_t)(kc * 64 + br_) * D_DIM + bcol;
        const uint32_t dstr = bs_b[buf] + br_ * 272;
#pragma unroll
        for (int c = 0; c < 4; c++)
            cp16(dstr + (bc_ + c) * 16, srcr + (bc_ + c) * 8);
    };

    // accumulators: [m-block][n8-tile][4], m16n8 layout per tile
    float acc[2][8][4];
#pragma unroll
    for (int mb = 0; mb < 2; mb++)
#pragma unroll
        for (int nt = 0; nt < 8; nt++)
#pragma unroll
            for (int e = 0; e < 4; e++) acc[mb][nt][e] = 0.f;

    issueA(0, 0);
    issueB(0, 0);
    CP_COMMIT();

    for (int kc = 0; kc < 16; kc++) {
        const int buf = kc & 1;
        if (kc + 1 < 16) {
            issueA(buf ^ 1, kc + 1);
            issueB(buf ^ 1, kc + 1);
            CP_COMMIT();
            CP_WAIT1();
        } else {
            CP_WAIT0();
        }
        __syncthreads();

        const uint32_t ab = as_b[buf];
        const uint32_t bb = bs_b[buf];
        // per k-step: load A frags for both m-blocks, B via ldsm4t, 16 mma
#pragma unroll
        for (int s = 0; s < 4; s++) {
            uint32_t af[2][4];
#pragma unroll
            for (int mb = 0; mb < 2; mb++) {
                const uint32_t aaddr = ab
                    + (wm0 + mb * 16 + (lane & 15)) * 144
                    + ((lane >> 4) * 8 + s * 16) * 2;
                ldsm4(af[mb][0], af[mb][1], af[mb][2], af[mb][3], aaddr);
            }
            const uint32_t vrow = s * 16 + ((lane >> 3) & 1) * 8 + (lane & 7);
#pragma unroll
            for (int np = 0; np < 4; np++) {
                uint32_t v0, v1, v2, v3;
                ldsm4t(v0, v1, v2, v3,
                       bb + vrow * 272 + (wnc + np * 2 + (lane >> 4)) * 16);
#pragma unroll
                for (int mb = 0; mb < 2; mb++) {
                    mma16(acc[mb][np * 2],     af[mb][0], af[mb][1],
                          af[mb][2], af[mb][3], v0, v1);
                    mma16(acc[mb][np * 2 + 1], af[mb][0], af[mb][1],
                          af[mb][2], af[mb][3], v2, v3);
                }
            }
        }
        __syncthreads();   // readers done before next prefetch overwrites buf
    }

    // ---- epilogue straight from registers (m16n8 layout) ----
    const float oscale = (!IS_O && z == 0) ? QSCALE : 1.0f;
#pragma unroll
    for (int mb = 0; mb < 2; mb++) {
        const int row0 = brow + wm0 + mb * 16 + g;
        const int row1 = row0 + 8;
#pragma unroll
        for (int nt = 0; nt < 8; nt++) {
            const int col = bcol + wn0 + nt * 8 + 2 * t;
            const float2 bi = *(const float2*)(bias + col);
            float v0 = (acc[mb][nt][0] + bi.x) * oscale;
            float v1 = (acc[mb][nt][1] + bi.y) * oscale;
            float v2 = (acc[mb][nt][2] + bi.x) * oscale;
            float v3 = (acc[mb][nt][3] + bi.y) * oscale;
            if (IS_O) {
                const float2 r0 = *(const float2*)(resid + (size_t)row0 * D_DIM + col);
                const float2 r1 = *(const float2*)(resid + (size_t)row1 * D_DIM + col);
                *(float2*)(g_x + (size_t)row0 * D_DIM + col) =
                    make_float2(v0 + r0.x, v1 + r0.y);
                *(float2*)(g_x + (size_t)row1 * D_DIM + col) =
                    make_float2(v2 + r1.x, v3 + r1.y);
            } else {
                __nv_bfloat16* dst = (z == 0) ? g_q : (z == 1) ? g_k : g_v;
                const int hh = col >> 6;
                const int d = col & 63;
                const int b0i = row0 >> 11, s0 = row0 & 2047;
                const int b1i = row1 >> 11, s1 = row1 & 2047;
                *(uint32_t*)(dst + (((size_t)(b0i * NHEAD + hh) * S_LEN) + s0) * HD + d) =
                    packbf(v0, v1);
                *(uint32_t*)(dst + (((size_t)(b1i * NHEAD + hh) * S_LEN) + s1) * HD + d) =
                    packbf(v2, v3);
            }
        }
    }
}

// ===========================================================================
// Flash attention (exact R10 version, 133.9 us): 8 warps x 16 q-rows, 256 thr,
// 2 CTAs/SM, 64-key KV tiles, Q-region overlay as KV stage 1. Max-free log2
// softmax, packed bf16x2 ex2, ones-MMA row sums.
// ===========================================================================
#define ATTN_SMEM_BYTES (2 * 18432)
#define ONESB 0x3F803F80u   // bf16x2 {1.0, 1.0}

__global__ __launch_bounds__(256, 2) void attn_k()
{
    extern __shared__ __nv_bfloat16 smh[];
    const uint32_t base = smem_u32(smh);
    const uint32_t qs_b = base;
    uint32_t ks_b[2], vs_b[2];
    ks_b[0] = base + 18432;
    vs_b[0] = base + 18432 + 9216;
    ks_b[1] = base;
    vs_b[1] = base + 9216;

    const int tid = threadIdx.x;
    const int lane = tid & 31;
    const int wid = tid >> 5;
    const int g = lane >> 2;
    const int t = lane & 3;

    const int bh = blockIdx.y;
    const int b = bh >> 4;
    const int h = bh & 15;
    const int q0 = blockIdx.x * 128;

    const __nv_bfloat16* qg = g_q + (size_t)bh * S_LEN * HD + (size_t)q0 * HD;
    const __nv_bfloat16* kg = g_k + (size_t)bh * S_LEN * HD;
    const __nv_bfloat16* vg = g_v + (size_t)bh * S_LEN * HD;

#pragma unroll
    for (int j = 0; j < 4; j++) {
        const int lin = tid + j * 256;
        const int r = lin >> 3;
        const int c8 = lin & 7;
        cp16(qs_b + r * 144 + c8 * 16, qg + r * 64 + c8 * 8);
    }
#pragma unroll
    for (int j = 0; j < 2; j++) {
        const int lin = tid + j * 256;
        const int r = lin >> 3;
        const int c8 = lin & 7;
        cp16(ks_b[0] + r * 144 + c8 * 16, kg + r * 64 + c8 * 8);
        cp16(vs_b[0] + r * 144 + c8 * 16, vg + r * 64 + c8 * 8);
    }
    CP_COMMIT();
    CP_WAIT0();
    __syncthreads();

    const int wrow = wid * 16;
    uint32_t qa[4][4];
#pragma unroll
    for (int s = 0; s < 4; s++) {
        const uint32_t a = qs_b + (wrow + (lane & 15)) * 144
                         + ((lane >> 4) * 8 + s * 16) * 2;
        ldsm4(qa[s][0], qa[s][1], qa[s][2], qa[s][3], a);
    }
    __syncthreads();

    float o[8][4];
#pragma unroll
    for (int nt = 0; nt < 8; nt++)
#pragma unroll
        for (int e = 0; e < 4; e++) o[nt][e] = 0.f;
    float lsum[4] = {0.f, 0.f, 0.f, 0.f};

    const int row0 = q0 + wrow + g;
    const int row1 = row0 + 8;
    const uint32_t* mb0 = g_mbits + (size_t)(b * S_LEN + row0) * (S_LEN / 32);
    const uint32_t* mb1 = g_mbits + (size_t)(b * S_LEN + row1) * (S_LEN / 32);

    for (int t0 = 0; t0 < 32; t0++) {
        if (t0 + 1 < 32) {
            const int nb = (t0 + 1) & 1;
            const size_t off = (size_t)(t0 + 1) * 64 * 64;
#pragma unroll
            for (int j = 0; j < 2; j++) {
                const int lin = tid + j * 256;
                const int r = lin >> 3;
                const int c8 = lin & 7;
                cp16(ks_b[nb] + r * 144 + c8 * 16, kg + off + r * 64 + c8 * 8);
                cp16(vs_b[nb] + r * 144 + c8 * 16, vg + off + r * 64 + c8 * 8);
            }
            CP_COMMIT();
        }

        const uint32_t kb = ks_b[t0 & 1];
        const uint32_t vb = vs_b[t0 & 1];

        float sacc[8][4];
#pragma unroll
        for (int nt = 0; nt < 8; nt++) {
            sacc[nt][0] = 0.f; sacc[nt][1] = 0.f;
            sacc[nt][2] = 0.f; sacc[nt][3] = 0.f;
            uint32_t kf[8];
            const uint32_t kaddr = kb + (nt * 8 + (lane & 7)) * 144 + (lane >> 3) * 16;
            ldsm4(kf[0], kf[1], kf[2], kf[3], kaddr);
            ldsm4(kf[4], kf[5], kf[6], kf[7], kaddr + 64);
#pragma unroll
            for (int s = 0; s < 4; s++)
                mma16(sacc[nt], qa[s][0], qa[s][1], qa[s][2], qa[s][3],
                      kf[2 * s], kf[2 * s + 1]);
        }

        const uint2 mw0 = *(const uint2*)(mb0 + t0 * 2);
        const uint2 mw1 = *(const uint2*)(mb1 + t0 * 2);
        const uint32_t t2 = 2 * t;
        const uint32_t s0x = mw0.x >> t2, s0y = mw0.y >> t2;
        const uint32_t s1x = mw1.x >> t2, s1y = mw1.y >> t2;
        uint32_t pp[8][2];
#pragma unroll
        for (int nt = 0; nt < 8; nt++) {
            const uint32_t w0 = (nt < 4) ? s0x : s0y;
            const uint32_t w1 = (nt < 4) ? s1x : s1y;
            const uint32_t bit0 = 1u << ((nt & 3) * 8);
            const uint32_t bit1 = 2u << ((nt & 3) * 8);
            const float v0 = (w0 & bit0) ? -130.f : sacc[nt][0];
            const float v1 = (w0 & bit1) ? -130.f : sacc[nt][1];
            const float v2 = (w1 & bit0) ? -130.f : sacc[nt][2];
            const float v3 = (w1 & bit1) ? -130.f : sacc[nt][3];
            pp[nt][0] = ex2bf2(packbf(v0, v1));
            pp[nt][1] = ex2bf2(packbf(v2, v3));
        }

#pragma unroll
        for (int s = 0; s < 4; s++) {
            const uint32_t a0 = pp[2 * s][0];
            const uint32_t a1 = pp[2 * s][1];
            const uint32_t a2 = pp[2 * s + 1][0];
            const uint32_t a3 = pp[2 * s + 1][1];
            mma16(lsum, a0, a1, a2, a3, ONESB, ONESB);
            const uint32_t vrow = s * 16 + ((lane >> 3) & 1) * 8 + (lane & 7);
#pragma unroll
            for (int np = 0; np < 4; np++) {
                uint32_t v0, v1, v2, v3;
                ldsm4t(v0, v1, v2, v3,
                       vb + vrow * 144 + (np * 2 + (lane >> 4)) * 16);
                mma16(o[np * 2],     a0, a1, a2, a3, v0, v1);
                mma16(o[np * 2 + 1], a0, a1, a2, a3, v2, v3);
            }
        }

        if (t0 + 1 < 32) {
            CP_WAIT0();
            __syncthreads();
        }
    }

    const float inv0 = 1.0f / lsum[0];
    const float inv1 = 1.0f / lsum[2];
#pragma unroll
    for (int nt = 0; nt < 8; nt++) {
        const int col = h * 64 + nt * 8 + 2 * t;
        *(uint32_t*)(g_ctx + (size_t)(b * S_LEN + row0) * D_DIM + col) =
            packbf(o[nt][0] * inv0, o[nt][1] * inv0);
        *(uint32_t*)(g_ctx + (size_t)(b * S_LEN + row1) * D_DIM + col) =
            packbf(o[nt][2] * inv1, o[nt][3] * inv1);
    }
}

// ---------------------------------------------------------------------------
// LayerNorm over last dim (1024), one block per row.
// ---------------------------------------------------------------------------
__global__ __launch_bounds__(256) void ln_k(const float* __restrict__ gamma,
                                            const float* __restrict__ beta,
                                            float* __restrict__ out)
{
    const int row = blockIdx.x;
    const int t = threadIdx.x;
    const float* x = g_x + (size_t)row * D_DIM;
    float4 xv = *(const float4*)(x + t * 4);
    float s  = (xv.x + xv.y) + (xv.z + xv.w);
    float sq = xv.x * xv.x + xv.y * xv.y + xv.z * xv.z + xv.w * xv.w;
#pragma unroll
    for (int off = 16; off; off >>= 1) {
        s  += __shfl_xor_sync(0xffffffffu, s, off);
        sq += __shfl_xor_sync(0xffffffffu, sq, off);
    }
    __shared__ float sh[16];
    const int w = t >> 5;
    if ((t & 31) == 0) { sh[w] = s; sh[8 + w] = sq; }
    __syncthreads();
    float st = 0.f, sqt = 0.f;
#pragma unroll
    for (int i = 0; i < 8; i++) { st += sh[i]; sqt += sh[8 + i]; }
    const float mu   = st * (1.0f / D_DIM);
    const float var  = sqt * (1.0f / D_DIM) - mu * mu;
    const float rstd = rsqrtf(var + 1e-5f);
    float4 g4 = *(const float4*)(gamma + t * 4);
    float4 b4 = *(const float4*)(beta + t * 4);
    float4 o;
    o.x = (xv.x - mu) * rstd * g4.x + b4.x;
    o.y = (xv.y - mu) * rstd * g4.y + b4.y;
    o.z = (xv.z - mu) * rstd * g4.z + b4.z;
    o.w = (xv.w - mu) * rstd * g4.w + b4.w;
    *(float4*)(out + (size_t)row * D_DIM + t * 4) = o;
}

// ---------------------------------------------------------------------------
extern "C" void kernel_launch(void* const* d_in, const int* in_sizes, int n_in,
                              void* d_out, int out_size)
{
    const float* Q   = (const float*)d_in[0];
    const float* Kin = (const float*)d_in[1];
    const float* V   = (const float*)d_in[2];
    const int*   mask = (const int*)d_in[3];
    const float* Wq = (const float*)d_in[4];
    const float* bq = (const float*)d_in[5];
    const float* Wk = (const float*)d_in[6];
    const float* bk = (const float*)d_in[7];
    const float* Wv = (const float*)d_in[8];
    const float* bv = (const float*)d_in[9];
    const float* Wo = (const float*)d_in[10];
    const float* bo = (const float*)d_in[11];
    const float* gamma = (const float*)d_in[12];
    const float* beta  = (const float*)d_in[13];
    float* out = (float*)d_out;

    cudaFuncSetAttribute(attn_k, cudaFuncAttributeMaxDynamicSharedMemorySize, ATTN_SMEM_BYTES);
    cudaFuncSetAttribute(mm3_k<0>, cudaFuncAttributeMaxDynamicSharedMemorySize, MM_SMEM_BYTES);
    cudaFuncSetAttribute(mm3_k<1>, cudaFuncAttributeMaxDynamicSharedMemorySize, MM_SMEM_BYTES);

    cvt_k<<<dim3(4096, 7), 256>>>(Q, Kin, V, Wq, Wk, Wv, Wo);
    mb_k<<<2 * S_LEN, 256>>>(mask);

    mm3_k<0><<<dim3(8, 32, 3), 256, MM_SMEM_BYTES>>>(bq, bk, bv, nullptr);
    attn_k<<<dim3(16, 32), 256, ATTN_SMEM_BYTES>>>();
    mm3_k<1><<<dim3(8, 32, 1), 256, MM_SMEM_BYTES>>>(bo, nullptr, nullptr, Q);
    ln_k<<<4096, 256>>>(gamma, beta, out);
}

// round 16
// speedup vs baseline: 1.1845x; 1.0356x over previous
#include <cuda_runtime.h>
#include <cuda_bf16.h>
#include <math.h>
#include <cstdint>

#define S_LEN 2048
#define D_DIM 1024
#define NHEAD 16
#define HD 64
#define MROWS 4096
// 0.125 (1/sqrt(64)) * log2(e), folded into the Q projection epilogue
#define QSCALE 0.1803368801111244f

// Scratch (device globals: no allocations allowed)
__device__ __nv_bfloat16 g_q[MROWS * D_DIM];    // [b,h,s,d] bf16, pre-scaled
__device__ __nv_bfloat16 g_k[MROWS * D_DIM];    // [b,h,s,d] bf16
__device__ __nv_bfloat16 g_v[MROWS * D_DIM];    // [b,h,s,d] bf16
__device__ __nv_bfloat16 g_ctx[MROWS * D_DIM];  // [b,s,h*64+d] bf16
__device__ float g_x[MROWS * D_DIM];            // pre-LN fp32
__device__ uint32_t g_mbits[2 * S_LEN * (S_LEN / 32)];  // packed mask bits
// bf16 copies of inputs & weights (cvt once, consumed by cp.async GEMMs)
__device__ __nv_bfloat16 g_qin[MROWS * D_DIM];
__device__ __nv_bfloat16 g_kin[MROWS * D_DIM];
__device__ __nv_bfloat16 g_vin[MROWS * D_DIM];
__device__ __nv_bfloat16 g_wbf[4 * D_DIM * D_DIM];

// ---------------------------------------------------------------------------
// helpers
// ---------------------------------------------------------------------------
__device__ __forceinline__ uint32_t smem_u32(const void* p) {
    return (uint32_t)__cvta_generic_to_shared(p);
}
__device__ __forceinline__ void cp16(uint32_t dst, const void* src) {
    asm volatile("cp.async.cg.shared.global [%0], [%1], 16;"
                 :: "r"(dst), "l"(src) : "memory");
}
#define CP_COMMIT() asm volatile("cp.async.commit_group;" ::: "memory")
#define CP_WAIT0()  asm volatile("cp.async.wait_group 0;" ::: "memory")

__device__ __forceinline__ void ldsm4(uint32_t& r0, uint32_t& r1,
                                      uint32_t& r2, uint32_t& r3, uint32_t a) {
    asm volatile("ldmatrix.sync.aligned.m8n8.x4.shared.b16 {%0,%1,%2,%3}, [%4];"
                 : "=r"(r0), "=r"(r1), "=r"(r2), "=r"(r3) : "r"(a));
}
__device__ __forceinline__ void ldsm4t(uint32_t& r0, uint32_t& r1,
                                       uint32_t& r2, uint32_t& r3, uint32_t a) {
    asm volatile("ldmatrix.sync.aligned.m8n8.x4.trans.shared.b16 {%0,%1,%2,%3}, [%4];"
                 : "=r"(r0), "=r"(r1), "=r"(r2), "=r"(r3) : "r"(a));
}
// D(16x8,f32) += A(16x16,bf16) * B(16x8,bf16)
__device__ __forceinline__ void mma16(float* d, uint32_t a0, uint32_t a1,
                                      uint32_t a2, uint32_t a3,
                                      uint32_t b0, uint32_t b1) {
    asm volatile(
        "mma.sync.aligned.m16n8k16.row.col.f32.bf16.bf16.f32 "
        "{%0,%1,%2,%3}, {%4,%5,%6,%7}, {%8,%9}, {%0,%1,%2,%3};"
        : "+f"(d[0]), "+f"(d[1]), "+f"(d[2]), "+f"(d[3])
        : "r"(a0), "r"(a1), "r"(a2), "r"(a3), "r"(b0), "r"(b1));
}
// pack two floats -> bf16x2 (lo in low 16 bits)
__device__ __forceinline__ uint32_t packbf(float lo, float hi) {
    uint32_t r;
    asm("cvt.rn.bf16x2.f32 %0, %1, %2;" : "=r"(r) : "f"(hi), "f"(lo));
    return r;
}
// packed 2^x on bf16x2 (subnormal results flushed to 0)
__device__ __forceinline__ uint32_t ex2bf2(uint32_t x) {
    uint32_t r;
    asm("ex2.approx.ftz.bf16x2 %0, %1;" : "=r"(r) : "r"(x));
    return r;
}

// ===========================================================================
// prep: z 0..2 cvt Q/K/V inputs; z 3..6 cvt weights; z 7 mask bit-pack.
// ===========================================================================
__global__ __launch_bounds__(256) void prep_k(
    const float* __restrict__ Q, const float* __restrict__ K,
    const float* __restrict__ V,
    const float* __restrict__ Wq, const float* __restrict__ Wk,
    const float* __restrict__ Wv, const float* __restrict__ Wo,
    const int* __restrict__ mask)
{
    const int z = blockIdx.y;
    if (z == 7) {
        // mask bit-pack: one block per row (4096 rows)
        const int rr = blockIdx.x;
        const int w = threadIdx.x >> 5;
        const int lane = threadIdx.x & 31;
        const int* mrow = mask + (size_t)rr * S_LEN;
        uint32_t* obase = g_mbits + (size_t)rr * (S_LEN / 32);
#pragma unroll
        for (int i = 0; i < 8; i++) {
            const int word = w + i * 8;
            const uint32_t bal =
                __ballot_sync(0xffffffffu, mrow[word * 32 + lane] != 0);
            if (lane == 0) obase[word] = bal;
        }
        return;
    }
    const float* src;
    __nv_bfloat16* dst;
    int n4;
    if (z < 3) {
        src = (z == 0) ? Q : (z == 1) ? K : V;
        dst = (z == 0) ? g_qin : (z == 1) ? g_kin : g_vin;
        n4 = (MROWS * D_DIM) / 4;
    } else {
        src = (z == 3) ? Wq : (z == 4) ? Wk : (z == 5) ? Wv : Wo;
        dst = g_wbf + (size_t)(z - 3) * (D_DIM * D_DIM);
        n4 = (D_DIM * D_DIM) / 4;
    }
    const int idx = blockIdx.x * 256 + threadIdx.x;
    if (idx >= n4) return;
    const float4 v = ((const float4*)src)[idx];
    uint2 p;
    p.x = packbf(v.x, v.y);
    p.y = packbf(v.z, v.w);
    ((uint2*)dst)[idx] = p;
}

// ===========================================================================
// bf16 GEMM, raw mma + ldsm, cp.async double-buffered, ONE sync per K-chunk
// (attn-style schedule: issue(k+1) -> compute(k) -> wait -> sync).
// C[4096x1024] = A @ W + bias. CTA 128x128, K-chunk 64, 8 warps of 32x64.
// Epilogue writes straight from accumulator registers.
// IS_O=0: blockIdx.z selects Q/K/V projection; Q result pre-scaled by QSCALE.
// IS_O=1: A=g_ctx, += fp32 resid -> g_x.
// smem: A0[0,18432) A1[18432,36864) B0[36864,54272) B1[54272,71680)
// ===========================================================================
#define MM_SMEM_BYTES 71680

template <int IS_O>
__global__ __launch_bounds__(256, 2) void mm3_k(
    const float* __restrict__ b0p, const float* __restrict__ b1p,
    const float* __restrict__ b2p, const float* __restrict__ resid)
{
    extern __shared__ __nv_bfloat16 smh[];
    const uint32_t sb = smem_u32(smh);
    const uint32_t as_b[2] = {sb, sb + 18432};
    const uint32_t bs_b[2] = {sb + 36864, sb + 36864 + 17408};

    const int tid = threadIdx.x;
    const int lane = tid & 31;
    const int wid = tid >> 5;
    const int g = lane >> 2;
    const int t = lane & 3;
    const int wm0 = (wid & 3) * 32;           // warp m offset (row)
    const int wn0 = (wid >> 2) * 64;          // warp n offset (col)
    const int wnc = (wid >> 2) * 8;           // warp n offset in 16B chunks
    const int brow = blockIdx.y * 128;
    const int bcol = blockIdx.x * 128;
    const int z = IS_O ? 3 : blockIdx.z;

    const __nv_bfloat16* A =
        IS_O ? g_ctx : (z == 0) ? g_qin : (z == 1) ? g_kin : g_vin;
    const __nv_bfloat16* W = g_wbf + (size_t)z * (D_DIM * D_DIM);
    const float* bias = IS_O ? b0p : (z == 0) ? b0p : (z == 1) ? b1p : b2p;

    const int ar = tid >> 1;
    const int ac = (tid & 1) * 4;
    const int br_ = tid >> 2;
    const int bc_ = (tid & 3) * 4;

    auto issueA = [&](int buf, int kc) {
        const __nv_bfloat16* srcr = A + (size_t)(brow + ar) * D_DIM + kc * 64;
        const uint32_t dstr = as_b[buf] + ar * 144;
#pragma unroll
        for (int c = 0; c < 4; c++)
            cp16(dstr + (ac + c) * 16, srcr + (ac + c) * 8);
    };
    auto issueB = [&](int buf, int kc) {
        const __nv_bfloat16* srcr = W + (size_t)(kc * 64 + br_) * D_DIM + bcol;
        const uint32_t dstr = bs_b[buf] + br_ * 272;
#pragma unroll
        for (int c = 0; c < 4; c++)
            cp16(dstr + (bc_ + c) * 16, srcr + (bc_ + c) * 8);
    };

    // accumulators: [m-block][n8-tile][4], m16n8 layout per tile
    float acc[2][8][4];
#pragma unroll
    for (int mb = 0; mb < 2; mb++)
#pragma unroll
        for (int nt = 0; nt < 8; nt++)
#pragma unroll
            for (int e = 0; e < 4; e++) acc[mb][nt][e] = 0.f;

    // prologue: load chunk 0, wait, sync (attn-style)
    issueA(0, 0);
    issueB(0, 0);
    CP_COMMIT();
    CP_WAIT0();
    __syncthreads();

    for (int kc = 0; kc < 16; kc++) {
        const int buf = kc & 1;
        // issue next chunk into the other buffer (safe: its readers all
        // passed the sync at the end of iteration kc-1)
        if (kc + 1 < 16) {
            issueA(buf ^ 1, kc + 1);
            issueB(buf ^ 1, kc + 1);
            CP_COMMIT();
        }

        const uint32_t ab = as_b[buf];
        const uint32_t bb = bs_b[buf];
#pragma unroll
        for (int s = 0; s < 4; s++) {
            uint32_t af[2][4];
#pragma unroll
            for (int mb = 0; mb < 2; mb++) {
                const uint32_t aaddr = ab
                    + (wm0 + mb * 16 + (lane & 15)) * 144
                    + ((lane >> 4) * 8 + s * 16) * 2;
                ldsm4(af[mb][0], af[mb][1], af[mb][2], af[mb][3], aaddr);
            }
            const uint32_t vrow = s * 16 + ((lane >> 3) & 1) * 8 + (lane & 7);
#pragma unroll
            for (int np = 0; np < 4; np++) {
                uint32_t v0, v1, v2, v3;
                ldsm4t(v0, v1, v2, v3,
                       bb + vrow * 272 + (wnc + np * 2 + (lane >> 4)) * 16);
#pragma unroll
                for (int mb = 0; mb < 2; mb++) {
                    mma16(acc[mb][np * 2],     af[mb][0], af[mb][1],
                          af[mb][2], af[mb][3], v0, v1);
                    mma16(acc[mb][np * 2 + 1], af[mb][0], af[mb][1],
                          af[mb][2], af[mb][3], v2, v3);
                }
            }
        }

        if (kc + 1 < 16) {
            CP_WAIT0();        // next chunk fully arrived
            __syncthreads();   // ONE barrier per chunk
        }
    }

    // ---- epilogue straight from registers (m16n8 layout) ----
    const float oscale = (!IS_O && z == 0) ? QSCALE : 1.0f;
#pragma unroll
    for (int mb = 0; mb < 2; mb++) {
        const int row0 = brow + wm0 + mb * 16 + g;
        const int row1 = row0 + 8;
#pragma unroll
        for (int nt = 0; nt < 8; nt++) {
            const int col = bcol + wn0 + nt * 8 + 2 * t;
            const float2 bi = *(const float2*)(bias + col);
            float v0 = (acc[mb][nt][0] + bi.x) * oscale;
            float v1 = (acc[mb][nt][1] + bi.y) * oscale;
            float v2 = (acc[mb][nt][2] + bi.x) * oscale;
            float v3 = (acc[mb][nt][3] + bi.y) * oscale;
            if (IS_O) {
                const float2 r0 = *(const float2*)(resid + (size_t)row0 * D_DIM + col);
                const float2 r1 = *(const float2*)(resid + (size_t)row1 * D_DIM + col);
                *(float2*)(g_x + (size_t)row0 * D_DIM + col) =
                    make_float2(v0 + r0.x, v1 + r0.y);
                *(float2*)(g_x + (size_t)row1 * D_DIM + col) =
                    make_float2(v2 + r1.x, v3 + r1.y);
            } else {
                __nv_bfloat16* dst = (z == 0) ? g_q : (z == 1) ? g_k : g_v;
                const int hh = col >> 6;
                const int d = col & 63;
                const int b0i = row0 >> 11, s0 = row0 & 2047;
                const int b1i = row1 >> 11, s1 = row1 & 2047;
                *(uint32_t*)(dst + (((size_t)(b0i * NHEAD + hh) * S_LEN) + s0) * HD + d) =
                    packbf(v0, v1);
                *(uint32_t*)(dst + (((size_t)(b1i * NHEAD + hh) * S_LEN) + s1) * HD + d) =
                    packbf(v2, v3);
            }
        }
    }
}

// ===========================================================================
// Flash attention (proven R10/R14 version): 8 warps x 16 q-rows, 256 thr,
// 2 CTAs/SM, 64-key KV tiles, Q-region overlay as KV stage 1. Max-free log2
// softmax, packed bf16x2 ex2, ones-MMA row sums.
// ===========================================================================
#define ATTN_SMEM_BYTES (2 * 18432)
#define ONESB 0x3F803F80u   // bf16x2 {1.0, 1.0}

__global__ __launch_bounds__(256, 2) void attn_k()
{
    extern __shared__ __nv_bfloat16 smh[];
    const uint32_t base = smem_u32(smh);
    const uint32_t qs_b = base;
    uint32_t ks_b[2], vs_b[2];
    ks_b[0] = base + 18432;
    vs_b[0] = base + 18432 + 9216;
    ks_b[1] = base;
    vs_b[1] = base + 9216;

    const int tid = threadIdx.x;
    const int lane = tid & 31;
    const int wid = tid >> 5;
    const int g = lane >> 2;
    const int t = lane & 3;

    const int bh = blockIdx.y;
    const int b = bh >> 4;
    const int h = bh & 15;
    const int q0 = blockIdx.x * 128;

    const __nv_bfloat16* qg = g_q + (size_t)bh * S_LEN * HD + (size_t)q0 * HD;
    const __nv_bfloat16* kg = g_k + (size_t)bh * S_LEN * HD;
    const __nv_bfloat16* vg = g_v + (size_t)bh * S_LEN * HD;

#pragma unroll
    for (int j = 0; j < 4; j++) {
        const int lin = tid + j * 256;
        const int r = lin >> 3;
        const int c8 = lin & 7;
        cp16(qs_b + r * 144 + c8 * 16, qg + r * 64 + c8 * 8);
    }
#pragma unroll
    for (int j = 0; j < 2; j++) {
        const int lin = tid + j * 256;
        const int r = lin >> 3;
        const int c8 = lin & 7;
        cp16(ks_b[0] + r * 144 + c8 * 16, kg + r * 64 + c8 * 8);
        cp16(vs_b[0] + r * 144 + c8 * 16, vg + r * 64 + c8 * 8);
    }
    CP_COMMIT();
    CP_WAIT0();
    __syncthreads();

    const int wrow = wid * 16;
    uint32_t qa[4][4];
#pragma unroll
    for (int s = 0; s < 4; s++) {
        const uint32_t a = qs_b + (wrow + (lane & 15)) * 144
                         + ((lane >> 4) * 8 + s * 16) * 2;
        ldsm4(qa[s][0], qa[s][1], qa[s][2], qa[s][3], a);
    }
    __syncthreads();

    float o[8][4];
#pragma unroll
    for (int nt = 0; nt < 8; nt++)
#pragma unroll
        for (int e = 0; e < 4; e++) o[nt][e] = 0.f;
    float lsum[4] = {0.f, 0.f, 0.f, 0.f};

    const int row0 = q0 + wrow + g;
    const int row1 = row0 + 8;
    const uint32_t* mb0 = g_mbits + (size_t)(b * S_LEN + row0) * (S_LEN / 32);
    const uint32_t* mb1 = g_mbits + (size_t)(b * S_LEN + row1) * (S_LEN / 32);

    for (int t0 = 0; t0 < 32; t0++) {
        if (t0 + 1 < 32) {
            const int nb = (t0 + 1) & 1;
            const size_t off = (size_t)(t0 + 1) * 64 * 64;
#pragma unroll
            for (int j = 0; j < 2; j++) {
                const int lin = tid + j * 256;
                const int r = lin >> 3;
                const int c8 = lin & 7;
                cp16(ks_b[nb] + r * 144 + c8 * 16, kg + off + r * 64 + c8 * 8);
                cp16(vs_b[nb] + r * 144 + c8 * 16, vg + off + r * 64 + c8 * 8);
            }
            CP_COMMIT();
        }

        const uint32_t kb = ks_b[t0 & 1];
        const uint32_t vb = vs_b[t0 & 1];

        float sacc[8][4];
#pragma unroll
        for (int nt = 0; nt < 8; nt++) {
            sacc[nt][0] = 0.f; sacc[nt][1] = 0.f;
            sacc[nt][2] = 0.f; sacc[nt][3] = 0.f;
            uint32_t kf[8];
            const uint32_t kaddr = kb + (nt * 8 + (lane & 7)) * 144 + (lane >> 3) * 16;
            ldsm4(kf[0], kf[1], kf[2], kf[3], kaddr);
            ldsm4(kf[4], kf[5], kf[6], kf[7], kaddr + 64);
#pragma unroll
            for (int s = 0; s < 4; s++)
                mma16(sacc[nt], qa[s][0], qa[s][1], qa[s][2], qa[s][3],
                      kf[2 * s], kf[2 * s + 1]);
        }

        const uint2 mw0 = *(const uint2*)(mb0 + t0 * 2);
        const uint2 mw1 = *(const uint2*)(mb1 + t0 * 2);
        const uint32_t t2 = 2 * t;
        const uint32_t s0x = mw0.x >> t2, s0y = mw0.y >> t2;
        const uint32_t s1x = mw1.x >> t2, s1y = mw1.y >> t2;
        uint32_t pp[8][2];
#pragma unroll
        for (int nt = 0; nt < 8; nt++) {
            const uint32_t w0 = (nt < 4) ? s0x : s0y;
            const uint32_t w1 = (nt < 4) ? s1x : s1y;
            const uint32_t bit0 = 1u << ((nt & 3) * 8);
            const uint32_t bit1 = 2u << ((nt & 3) * 8);
            const float v0 = (w0 & bit0) ? -130.f : sacc[nt][0];
            const float v1 = (w0 & bit1) ? -130.f : sacc[nt][1];
            const float v2 = (w1 & bit0) ? -130.f : sacc[nt][2];
            const float v3 = (w1 & bit1) ? -130.f : sacc[nt][3];
            pp[nt][0] = ex2bf2(packbf(v0, v1));
            pp[nt][1] = ex2bf2(packbf(v2, v3));
        }

#pragma unroll
        for (int s = 0; s < 4; s++) {
            const uint32_t a0 = pp[2 * s][0];
            const uint32_t a1 = pp[2 * s][1];
            const uint32_t a2 = pp[2 * s + 1][0];
            const uint32_t a3 = pp[2 * s + 1][1];
            mma16(lsum, a0, a1, a2, a3, ONESB, ONESB);
            const uint32_t vrow = s * 16 + ((lane >> 3) & 1) * 8 + (lane & 7);
#pragma unroll
            for (int np = 0; np < 4; np++) {
                uint32_t v0, v1, v2, v3;
                ldsm4t(v0, v1, v2, v3,
                       vb + vrow * 144 + (np * 2 + (lane >> 4)) * 16);
                mma16(o[np * 2],     a0, a1, a2, a3, v0, v1);
                mma16(o[np * 2 + 1], a0, a1, a2, a3, v2, v3);
            }
        }

        if (t0 + 1 < 32) {
            CP_WAIT0();
            __syncthreads();
        }
    }

    const float inv0 = 1.0f / lsum[0];
    const float inv1 = 1.0f / lsum[2];
#pragma unroll
    for (int nt = 0; nt < 8; nt++) {
        const int col = h * 64 + nt * 8 + 2 * t;
        *(uint32_t*)(g_ctx + (size_t)(b * S_LEN + row0) * D_DIM + col) =
            packbf(o[nt][0] * inv0, o[nt][1] * inv0);
        *(uint32_t*)(g_ctx + (size_t)(b * S_LEN + row1) * D_DIM + col) =
            packbf(o[nt][2] * inv1, o[nt][3] * inv1);
    }
}

// ---------------------------------------------------------------------------
// LayerNorm over last dim (1024), one block per row.
// ---------------------------------------------------------------------------
__global__ __launch_bounds__(256) void ln_k(const float* __restrict__ gamma,
                                            const float* __restrict__ beta,
                                            float* __restrict__ out)
{
    const int row = blockIdx.x;
    const int t = threadIdx.x;
    const float* x = g_x + (size_t)row * D_DIM;
    float4 xv = *(const float4*)(x + t * 4);
    float s  = (xv.x + xv.y) + (xv.z + xv.w);
    float sq = xv.x * xv.x + xv.y * xv.y + xv.z * xv.z + xv.w * xv.w;
#pragma unroll
    for (int off = 16; off; off >>= 1) {
        s  += __shfl_xor_sync(0xffffffffu, s, off);
        sq += __shfl_xor_sync(0xffffffffu, sq, off);
    }
    __shared__ float sh[16];
    const int w = t >> 5;
    if ((t & 31) == 0) { sh[w] = s; sh[8 + w] = sq; }
    __syncthreads();
    float st = 0.f, sqt = 0.f;
#pragma unroll
    for (int i = 0; i < 8; i++) { st += sh[i]; sqt += sh[8 + i]; }
    const float mu   = st * (1.0f / D_DIM);
    const float var  = sqt * (1.0f / D_DIM) - mu * mu;
    const float rstd = rsqrtf(var + 1e-5f);
    float4 g4 = *(const float4*)(gamma + t * 4);
    float4 b4 = *(const float4*)(beta + t * 4);
    float4 o;
    o.x = (xv.x - mu) * rstd * g4.x + b4.x;
    o.y = (xv.y - mu) * rstd * g4.y + b4.y;
    o.z = (xv.z - mu) * rstd * g4.z + b4.z;
    o.w = (xv.w - mu) * rstd * g4.w + b4.w;
    *(float4*)(out + (size_t)row * D_DIM + t * 4) = o;
}

// ---------------------------------------------------------------------------
extern "C" void kernel_launch(void* const* d_in, const int* in_sizes, int n_in,
                              void* d_out, int out_size)
{
    const float* Q   = (const float*)d_in[0];
    const float* Kin = (const float*)d_in[1];
    const float* V   = (const float*)d_in[2];
    const int*   mask = (const int*)d_in[3];
    const float* Wq = (const float*)d_in[4];
    const float* bq = (const float*)d_in[5];
    const float* Wk = (const float*)d_in[6];
    const float* bk = (const float*)d_in[7];
    const float* Wv = (const float*)d_in[8];
    const float* bv = (const float*)d_in[9];
    const float* Wo = (const float*)d_in[10];
    const float* bo = (const float*)d_in[11];
    const float* gamma = (const float*)d_in[12];
    const float* beta  = (const float*)d_in[13];
    float* out = (float*)d_out;

    cudaFuncSetAttribute(attn_k, cudaFuncAttributeMaxDynamicSharedMemorySize, ATTN_SMEM_BYTES);
    cudaFuncSetAttribute(mm3_k<0>, cudaFuncAttributeMaxDynamicSharedMemorySize, MM_SMEM_BYTES);
    cudaFuncSetAttribute(mm3_k<1>, cudaFuncAttributeMaxDynamicSharedMemorySize, MM_SMEM_BYTES);

    // prep: z 0..6 = cvt inputs/weights, z 7 = mask bit-pack (one launch)
    prep_k<<<dim3(4096, 8), 256>>>(Q, Kin, V, Wq, Wk, Wv, Wo, mask);

    mm3_k<0><<<dim3(8, 32, 3), 256, MM_SMEM_BYTES>>>(bq, bk, bv, nullptr);
    attn_k<<<dim3(16, 32), 256, ATTN_SMEM_BYTES>>>();
    mm3_k<1><<<dim3(8, 32, 1), 256, MM_SMEM_BYTES>>>(bo, nullptr, nullptr, Q);
    ln_k<<<4096, 256>>>(gamma, beta, out);
}